// round 9
// baseline (speedup 1.0000x reference)
#include <cuda_runtime.h>
#include <math.h>

// Problem dims
#define BSZ 2
#define SEQ 512
#define HID 1024
#define NHD 16
#define HDD 64
#define NL  4
#define FFD 4096
#define NCL 14
#define TOK (BSZ*SEQ)          // 1024
#define SHs (SEQ*HID)          // 524288
#define HSC (SEQ*SEQ)          // 262144

// ---------------- scratch (device globals: no cudaMalloc allowed) -------------
__device__ float g_x[TOK*HID];
__device__ float g_q[TOK*HID];
__device__ float g_k[TOK*HID];
__device__ float g_v[TOK*HID];
__device__ float g_rel[SEQ*HID];
__device__ float g_pk[SEQ*HID];
__device__ float g_pq[SEQ*HID];
__device__ float g_sc[BSZ*NHD*SEQ*SEQ];
__device__ float g_c2p[BSZ*NHD*SEQ*SEQ];
__device__ float g_p2c[BSZ*NHD*SEQ*SEQ];
__device__ float g_ctx[TOK*HID];
__device__ float g_ff[TOK*FFD];
__device__ int   g_idxm[SEQ*SEQ];
__device__ float g_nll[TOK];

// ---------------- job descriptors (passed in kernel params) -------------------
struct JobDesc { const float* A; const float* B; float* C; const float* bias; int M; int pad; };
template<int NJ> struct JobsP { JobDesc j[NJ]; };

// ---------------- block reduction helper --------------------------------------
__device__ __forceinline__ float blk_sum(float v, float* red) {
    #pragma unroll
    for (int o = 16; o; o >>= 1) v += __shfl_down_sync(0xffffffffu, v, o);
    int w = threadIdx.x >> 5, lane = threadIdx.x & 31;
    int nw = blockDim.x >> 5;
    __syncthreads();
    if (lane == 0) red[w] = v;
    __syncthreads();
    if (threadIdx.x == 0) { float s = 0.f; for (int i = 0; i < nw; i++) s += red[i]; red[0] = s; }
    __syncthreads();
    return red[0];
}

// ---------------- tf32 helpers ------------------------------------------------
__device__ __forceinline__ void split_tf32(float x, float& h, float& l) {
    unsigned u; asm("cvt.rna.tf32.f32 %0, %1;" : "=r"(u) : "f"(x));
    h = __uint_as_float(u);
    float r = x - h;
    unsigned v2; asm("cvt.rna.tf32.f32 %0, %1;" : "=r"(v2) : "f"(r));
    l = __uint_as_float(v2);
}

__device__ __forceinline__ void mma_tf32(float* d, const float* a, const float* b) {
    asm volatile(
        "mma.sync.aligned.m16n8k8.row.col.f32.tf32.tf32.f32 "
        "{%0,%1,%2,%3}, {%4,%5,%6,%7}, {%8,%9}, {%0,%1,%2,%3};\n"
        : "+f"(d[0]), "+f"(d[1]), "+f"(d[2]), "+f"(d[3])
        : "r"(__float_as_uint(a[0])), "r"(__float_as_uint(a[1])),
          "r"(__float_as_uint(a[2])), "r"(__float_as_uint(a[3])),
          "r"(__float_as_uint(b[0])), "r"(__float_as_uint(b[1])));
}

#define SMEM_BYTES   ((2*128*20*2 + 2*64*20*2) * 4)    // 61440 (128x64 kernel)
#define SMEM_BYTES2  ((2*128*20*2 + 2*128*20*2) * 4)   // 81920 (128x128 kernel)

// ======== 128x128 tensor-core GEMM (3xTF32, 512 threads, 4x4 warps) ===========
// Block tile 128(M) x 128(N), BK=16, warp tile 32x32, double-buffered smem.
// TB=true -> B given as [N,K] row-major (computes A @ B^T).
template<int ACT, bool TB, int NJ>
__global__ __launch_bounds__(512)
void tgemm512_k(JobsP<NJ> P, int K, int lda, int ldb, int ldc)
{
    const JobDesc jd = P.j[blockIdx.z];
    const int m0 = blockIdx.y << 7;
    if (m0 >= jd.M) return;
    const float* __restrict__ A  = jd.A;
    const float* __restrict__ Bm = jd.B;
    float* __restrict__ C = jd.C;
    const float* bias = jd.bias;
    const int n0 = blockIdx.x << 7;

    extern __shared__ float smem_[];
    float* AhS = smem_;                       // [2][128][20]
    float* AlS = AhS + 2*128*20;
    float* BhS = AlS + 2*128*20;              // [2][128][20]
    float* BlS = BhS + 2*128*20;

    const int tid  = threadIdx.x;
    const int warp = tid >> 5, lane = tid & 31;
    const int wm = warp >> 2;          // 0..3
    const int wn = warp & 3;           // 0..3
    const int g  = lane >> 2;          // 0..7
    const int t  = lane & 3;           // 0..3

    const int ar  = tid >> 2;                // 0..127
    const int ac  = (tid & 3) << 2;          // 0,4,8,12
    const int brk = tid >> 5;                // 0..15   (!TB)
    const int bcn = (tid & 31) << 2;         // 0..124

    float acc[2][4][4] = {};
    float4 ra, rb;

    // ---- prologue: k-tile 0 -> regs -> split -> stage 0 ----
    ra = *(const float4*)(A + (long)(m0 + ar) * lda + ac);
    if (TB) rb = *(const float4*)(Bm + (long)(n0 + ar) * ldb + ac);
    else    rb = *(const float4*)(Bm + (long)brk * ldb + n0 + bcn);
    {
        float* dh = AhS + (long)ar * 20 + ac;
        float* dl = AlS + (long)ar * 20 + ac;
        float av[4] = {ra.x, ra.y, ra.z, ra.w};
        #pragma unroll
        for (int i = 0; i < 4; i++) { float h,l; split_tf32(av[i],h,l); dh[i]=h; dl[i]=l; }
        float bv[4] = {rb.x, rb.y, rb.z, rb.w};
        if (TB) {
            float* eh = BhS + (long)ar * 20 + ac;
            float* el = BlS + (long)ar * 20 + ac;
            #pragma unroll
            for (int i = 0; i < 4; i++) { float h,l; split_tf32(bv[i],h,l); eh[i]=h; el[i]=l; }
        } else {
            #pragma unroll
            for (int i = 0; i < 4; i++) { float h,l; split_tf32(bv[i],h,l);
                BhS[(long)(bcn+i)*20 + brk] = h; BlS[(long)(bcn+i)*20 + brk] = l; }
        }
    }
    __syncthreads();

    const int KT = K >> 4;
    for (int kt = 0; kt < KT; kt++) {
        const int st = kt & 1;
        const bool more = (kt + 1 < KT);
        if (more) {
            int k0 = (kt + 1) << 4;
            ra = *(const float4*)(A + (long)(m0 + ar) * lda + k0 + ac);
            if (TB) rb = *(const float4*)(Bm + (long)(n0 + ar) * ldb + k0 + ac);
            else    rb = *(const float4*)(Bm + (long)(k0 + brk) * ldb + n0 + bcn);
        }
        const float* pAh = AhS + st * 128 * 20;
        const float* pAl = AlS + st * 128 * 20;
        const float* pBh = BhS + st * 128 * 20;
        const float* pBl = BlS + st * 128 * 20;
        #pragma unroll
        for (int ks = 0; ks < 16; ks += 8) {
            float ah[2][4], al[2][4], bh[4][2], bl[4][2];
            #pragma unroll
            for (int mt = 0; mt < 2; mt++) {
                int mr = (wm << 5) + (mt << 4);
                ah[mt][0] = pAh[(mr+g)*20 + ks+t];
                ah[mt][1] = pAh[(mr+g+8)*20 + ks+t];
                ah[mt][2] = pAh[(mr+g)*20 + ks+t+4];
                ah[mt][3] = pAh[(mr+g+8)*20 + ks+t+4];
                al[mt][0] = pAl[(mr+g)*20 + ks+t];
                al[mt][1] = pAl[(mr+g+8)*20 + ks+t];
                al[mt][2] = pAl[(mr+g)*20 + ks+t+4];
                al[mt][3] = pAl[(mr+g+8)*20 + ks+t+4];
            }
            #pragma unroll
            for (int nt = 0; nt < 4; nt++) {
                int nc = (wn << 5) + (nt << 3) + g;
                bh[nt][0] = pBh[nc*20 + ks+t];
                bh[nt][1] = pBh[nc*20 + ks+t+4];
                bl[nt][0] = pBl[nc*20 + ks+t];
                bl[nt][1] = pBl[nc*20 + ks+t+4];
            }
            #pragma unroll
            for (int mt = 0; mt < 2; mt++)
                #pragma unroll
                for (int nt = 0; nt < 4; nt++) mma_tf32(acc[mt][nt], ah[mt], bh[nt]);
            #pragma unroll
            for (int mt = 0; mt < 2; mt++)
                #pragma unroll
                for (int nt = 0; nt < 4; nt++) mma_tf32(acc[mt][nt], ah[mt], bl[nt]);
            #pragma unroll
            for (int mt = 0; mt < 2; mt++)
                #pragma unroll
                for (int nt = 0; nt < 4; nt++) mma_tf32(acc[mt][nt], al[mt], bh[nt]);
        }
        if (more) {
            const int s2 = (kt + 1) & 1;
            float* dh = AhS + ((long)s2*128 + ar)*20 + ac;
            float* dl = AlS + ((long)s2*128 + ar)*20 + ac;
            float av[4] = {ra.x, ra.y, ra.z, ra.w};
            #pragma unroll
            for (int i = 0; i < 4; i++) { float h,l; split_tf32(av[i],h,l); dh[i]=h; dl[i]=l; }
            float bv[4] = {rb.x, rb.y, rb.z, rb.w};
            if (TB) {
                float* eh = BhS + ((long)s2*128 + ar)*20 + ac;
                float* el = BlS + ((long)s2*128 + ar)*20 + ac;
                #pragma unroll
                for (int i = 0; i < 4; i++) { float h,l; split_tf32(bv[i],h,l); eh[i]=h; el[i]=l; }
            } else {
                #pragma unroll
                for (int i = 0; i < 4; i++) { float h,l; split_tf32(bv[i],h,l);
                    BhS[((long)s2*128 + bcn+i)*20 + brk] = h; BlS[((long)s2*128 + bcn+i)*20 + brk] = l; }
            }
        }
        __syncthreads();
    }

    // epilogue
    #pragma unroll
    for (int mt = 0; mt < 2; mt++) {
        #pragma unroll
        for (int nt = 0; nt < 4; nt++) {
            int col = n0 + (wn << 5) + (nt << 3) + (t << 1);
            float b0 = bias ? bias[col]     : 0.f;
            float b1 = bias ? bias[col + 1] : 0.f;
            #pragma unroll
            for (int half = 0; half < 2; half++) {
                int row = m0 + (wm << 5) + (mt << 4) + g + (half << 3);
                float v0 = acc[mt][nt][half * 2 + 0] + b0;
                float v1 = acc[mt][nt][half * 2 + 1] + b1;
                if (ACT == 1) {
                    v0 = 0.5f * v0 * (1.0f + erff(v0 * 0.70710678118654752f));
                    v1 = 0.5f * v1 * (1.0f + erff(v1 * 0.70710678118654752f));
                }
                *(float2*)(C + (long)row * ldc + col) = make_float2(v0, v1);
            }
        }
    }
}

// ======== 128x64 tensor-core GEMM (3xTF32, 256 threads) — ctx only ============
template<int ACT, bool TB, int NJ>
__global__ __launch_bounds__(256)
void tgemm_k(JobsP<NJ> P, int K, int lda, int ldb, int ldc)
{
    const JobDesc jd = P.j[blockIdx.z];
    const int m0 = blockIdx.y << 7;
    if (m0 >= jd.M) return;
    const float* __restrict__ A  = jd.A;
    const float* __restrict__ Bm = jd.B;
    float* __restrict__ C = jd.C;
    const float* bias = jd.bias;
    const int n0 = blockIdx.x << 6;

    extern __shared__ float smem_[];
    float* AhS = smem_;
    float* AlS = AhS + 2*128*20;
    float* BhS = AlS + 2*128*20;
    float* BlS = BhS + 2*64*20;

    const int tid  = threadIdx.x;
    const int warp = tid >> 5, lane = tid & 31;
    const int wm = warp >> 1;
    const int wn = warp & 1;
    const int g  = lane >> 2;
    const int t  = lane & 3;

    const int ar  = tid >> 1;
    const int ac  = (tid & 1) << 3;
    const int brn = tid >> 2;
    const int bck = (tid & 3) << 2;
    const int brk = tid >> 4;
    const int bcn = (tid & 15) << 2;

    float acc[2][4][4] = {};
    float4 ra0, ra1, rbv;

    {
        const float* Ap = A + (long)(m0 + ar) * lda + ac;
        ra0 = *(const float4*)Ap; ra1 = *(const float4*)(Ap + 4);
        if (TB) rbv = *(const float4*)(Bm + (long)(n0 + brn) * ldb + bck);
        else    rbv = *(const float4*)(Bm + (long)brk * ldb + n0 + bcn);
    }
    {
        float* dh = AhS + (long)ar * 20 + ac;
        float* dl = AlS + (long)ar * 20 + ac;
        float hv[8] = {ra0.x,ra0.y,ra0.z,ra0.w, ra1.x,ra1.y,ra1.z,ra1.w};
        #pragma unroll
        for (int i = 0; i < 8; i++) { float h,l; split_tf32(hv[i],h,l); dh[i]=h; dl[i]=l; }
        float bv[4] = {rbv.x,rbv.y,rbv.z,rbv.w};
        if (TB) {
            float* eh = BhS + (long)brn * 20 + bck;
            float* el = BlS + (long)brn * 20 + bck;
            #pragma unroll
            for (int i = 0; i < 4; i++) { float h,l; split_tf32(bv[i],h,l); eh[i]=h; el[i]=l; }
        } else {
            #pragma unroll
            for (int i = 0; i < 4; i++) { float h,l; split_tf32(bv[i],h,l);
                BhS[(long)(bcn+i)*20 + brk] = h; BlS[(long)(bcn+i)*20 + brk] = l; }
        }
    }
    __syncthreads();

    const int KT = K >> 4;
    for (int kt = 0; kt < KT; kt++) {
        const int st = kt & 1;
        const bool more = (kt + 1 < KT);
        if (more) {
            int k0 = (kt + 1) << 4;
            const float* Ap = A + (long)(m0 + ar) * lda + k0 + ac;
            ra0 = *(const float4*)Ap; ra1 = *(const float4*)(Ap + 4);
            if (TB) rbv = *(const float4*)(Bm + (long)(n0 + brn) * ldb + k0 + bck);
            else    rbv = *(const float4*)(Bm + (long)(k0 + brk) * ldb + n0 + bcn);
        }
        const float* pAh = AhS + st * 128 * 20;
        const float* pAl = AlS + st * 128 * 20;
        const float* pBh = BhS + st * 64 * 20;
        const float* pBl = BlS + st * 64 * 20;
        #pragma unroll
        for (int ks = 0; ks < 16; ks += 8) {
            float ah[2][4], al[2][4], bh[4][2], bl[4][2];
            #pragma unroll
            for (int mt = 0; mt < 2; mt++) {
                int mr = (wm << 5) + (mt << 4);
                ah[mt][0] = pAh[(mr+g)*20 + ks+t];
                ah[mt][1] = pAh[(mr+g+8)*20 + ks+t];
                ah[mt][2] = pAh[(mr+g)*20 + ks+t+4];
                ah[mt][3] = pAh[(mr+g+8)*20 + ks+t+4];
                al[mt][0] = pAl[(mr+g)*20 + ks+t];
                al[mt][1] = pAl[(mr+g+8)*20 + ks+t];
                al[mt][2] = pAl[(mr+g)*20 + ks+t+4];
                al[mt][3] = pAl[(mr+g+8)*20 + ks+t+4];
            }
            #pragma unroll
            for (int nt = 0; nt < 4; nt++) {
                int nc = (wn << 5) + (nt << 3) + g;
                bh[nt][0] = pBh[nc*20 + ks+t];
                bh[nt][1] = pBh[nc*20 + ks+t+4];
                bl[nt][0] = pBl[nc*20 + ks+t];
                bl[nt][1] = pBl[nc*20 + ks+t+4];
            }
            #pragma unroll
            for (int mt = 0; mt < 2; mt++)
                #pragma unroll
                for (int nt = 0; nt < 4; nt++) mma_tf32(acc[mt][nt], ah[mt], bh[nt]);
            #pragma unroll
            for (int mt = 0; mt < 2; mt++)
                #pragma unroll
                for (int nt = 0; nt < 4; nt++) mma_tf32(acc[mt][nt], ah[mt], bl[nt]);
            #pragma unroll
            for (int mt = 0; mt < 2; mt++)
                #pragma unroll
                for (int nt = 0; nt < 4; nt++) mma_tf32(acc[mt][nt], al[mt], bh[nt]);
        }
        if (more) {
            const int s2 = (kt + 1) & 1;
            float* dh = AhS + ((long)s2*128 + ar)*20 + ac;
            float* dl = AlS + ((long)s2*128 + ar)*20 + ac;
            float hv[8] = {ra0.x,ra0.y,ra0.z,ra0.w, ra1.x,ra1.y,ra1.z,ra1.w};
            #pragma unroll
            for (int i = 0; i < 8; i++) { float h,l; split_tf32(hv[i],h,l); dh[i]=h; dl[i]=l; }
            float bv[4] = {rbv.x,rbv.y,rbv.z,rbv.w};
            if (TB) {
                float* eh = BhS + ((long)s2*64 + brn)*20 + bck;
                float* el = BlS + ((long)s2*64 + brn)*20 + bck;
                #pragma unroll
                for (int i = 0; i < 4; i++) { float h,l; split_tf32(bv[i],h,l); eh[i]=h; el[i]=l; }
            } else {
                #pragma unroll
                for (int i = 0; i < 4; i++) { float h,l; split_tf32(bv[i],h,l);
                    BhS[((long)s2*64 + bcn+i)*20 + brk] = h; BlS[((long)s2*64 + bcn+i)*20 + brk] = l; }
            }
        }
        __syncthreads();
    }

    #pragma unroll
    for (int mt = 0; mt < 2; mt++) {
        #pragma unroll
        for (int nt = 0; nt < 4; nt++) {
            int col = n0 + (wn << 5) + (nt << 3) + (t << 1);
            float b0 = bias ? bias[col]     : 0.f;
            float b1 = bias ? bias[col + 1] : 0.f;
            #pragma unroll
            for (int half = 0; half < 2; half++) {
                int row = m0 + (wm << 5) + (mt << 4) + g + (half << 3);
                float v0 = acc[mt][nt][half * 2 + 0] + b0;
                float v1 = acc[mt][nt][half * 2 + 1] + b1;
                if (ACT == 1) {
                    v0 = 0.5f * v0 * (1.0f + erff(v0 * 0.70710678118654752f));
                    v1 = 0.5f * v1 * (1.0f + erff(v1 * 0.70710678118654752f));
                }
                *(float2*)(C + (long)row * ldc + col) = make_float2(v0, v1);
            }
        }
    }
}

// ---------------- embedding: x = LN(word_emb[id]) * maskf ---------------------
__global__ void embed_ln_k(const float* __restrict__ emb,
                           const float* __restrict__ s, const float* __restrict__ b,
                           const int* __restrict__ ids, const int* __restrict__ am,
                           float* __restrict__ out)
{
    __shared__ float sh[HID];
    __shared__ float red[8];
    int tok = blockIdx.x;
    long ebase = (long)ids[tok] * HID;
    float m = (float)am[tok];
    float ls = 0.f;
    for (int i = threadIdx.x; i < HID; i += blockDim.x) { float v = emb[ebase + i]; sh[i] = v; ls += v; }
    __syncthreads();
    float mu = blk_sum(ls, red) * (1.0f / HID);
    float lv = 0.f;
    for (int i = threadIdx.x; i < HID; i += blockDim.x) { float d = sh[i] - mu; lv += d * d; }
    float var = blk_sum(lv, red) * (1.0f / HID);
    float r = rsqrtf(var + 1e-7f);
    long obase = (long)tok * HID;
    for (int i = threadIdx.x; i < HID; i += blockDim.x)
        out[obase + i] = ((sh[i] - mu) * r * s[i] + b[i]) * m;
}

// ---------------- residual + LN: out = LN((res?) + t) -------------------------
__global__ void add_ln_k(const float* res, const float* __restrict__ t,
                         const float* __restrict__ s, const float* __restrict__ b,
                         float* out)
{
    __shared__ float sh[HID];
    __shared__ float red[8];
    long base = (long)blockIdx.x * HID;
    float ls = 0.f;
    for (int i = threadIdx.x; i < HID; i += blockDim.x) {
        float v = t[base + i];
        if (res) v += res[base + i];
        sh[i] = v; ls += v;
    }
    __syncthreads();
    float mu = blk_sum(ls, red) * (1.0f / HID);
    float lv = 0.f;
    for (int i = threadIdx.x; i < HID; i += blockDim.x) { float d = sh[i] - mu; lv += d * d; }
    float var = blk_sum(lv, red) * (1.0f / HID);
    float r = rsqrtf(var + 1e-7f);
    for (int i = threadIdx.x; i < HID; i += blockDim.x)
        out[base + i] = (sh[i] - mu) * r * s[i] + b[i];
}

// ---------------- DeBERTa log-bucket relative index ---------------------------
__global__ void build_idx_k(int* __restrict__ idxm)
{
    int q = blockIdx.x;
    const int mid = 128;
    for (int k = threadIdx.x; k < SEQ; k += blockDim.x) {
        int rel = q - k;
        int a = (rel < mid && rel > -mid) ? (mid - 1) : (rel < 0 ? -rel : rel);
        int bucket;
        if (a <= mid) bucket = rel;
        else {
            float lp = ceilf(logf((float)a / (float)mid) / logf(511.0f / (float)mid) * (float)(mid - 1))
                       + (float)mid;
            float sgn = (rel > 0) ? 1.f : ((rel < 0) ? -1.f : 0.f);
            bucket = (int)(lp * sgn);
        }
        int J = bucket + 256;
        J = J < 0 ? 0 : (J > 511 ? 511 : J);
        idxm[q * SEQ + k] = J;
    }
}

// ------- combine + mask + softmax:  probs = softmax((qk + c2p[J] + p2c[J])/scale)
__global__ void attn_softmax_k(float* __restrict__ sc, const float* __restrict__ c2p,
                               const float* __restrict__ p2c, const int* __restrict__ idxm,
                               const int* __restrict__ am)
{
    __shared__ float red[4];
    int q = blockIdx.x, z = blockIdx.y;
    int b = z >> 4;
    long ro = ((long)z * SEQ + q) * (long)SEQ;
    float* row = sc + ro;
    const float* cr = c2p + ro;
    const float* pb = p2c + (long)z * SEQ * 512;
    int mq = am[b * SEQ + q];
    const float scale = sqrtf(3.0f * (float)HDD);
    float vals[4]; int msk[4];
    float mx = -3.402823466e38f;
    #pragma unroll
    for (int t = 0; t < 4; t++) {
        int k = threadIdx.x + t * 128;
        int J = idxm[q * SEQ + k];
        float v = (row[k] + cr[J] + pb[(long)k * 512 + J]) / scale;
        int mk = mq & am[b * SEQ + k];
        vals[t] = v; msk[t] = mk;
        if (mk) mx = fmaxf(mx, v);
    }
    #pragma unroll
    for (int o = 16; o; o >>= 1) mx = fmaxf(mx, __shfl_down_sync(0xffffffffu, mx, o));
    if ((threadIdx.x & 31) == 0) red[threadIdx.x >> 5] = mx;
    __syncthreads();
    mx = fmaxf(fmaxf(red[0], red[1]), fmaxf(red[2], red[3]));
    float ls = 0.f;
    #pragma unroll
    for (int t = 0; t < 4; t++) {
        float e = msk[t] ? expf(vals[t] - mx) : 0.f;
        vals[t] = e; ls += e;
    }
    __syncthreads();
    #pragma unroll
    for (int o = 16; o; o >>= 1) ls += __shfl_down_sync(0xffffffffu, ls, o);
    if ((threadIdx.x & 31) == 0) red[threadIdx.x >> 5] = ls;
    __syncthreads();
    float sum = red[0] + red[1] + red[2] + red[3];
    float inv = sum > 0.f ? 1.0f / sum : 0.f;
    #pragma unroll
    for (int t = 0; t < 4; t++) row[threadIdx.x + t * 128] = vals[t] * inv;
}

// ---------------- decoder (N=14) + per-row masked NLL -------------------------
__global__ void decoder_k(const float* __restrict__ t, const float* __restrict__ Wd,
                          const float* __restrict__ bd, const int* __restrict__ labels,
                          const int* __restrict__ am, float* __restrict__ out,
                          int logit_limit, float* __restrict__ nll)
{
    __shared__ float sh[HID];
    __shared__ float wred[4][NCL];
    __shared__ float lg[NCL];
    int row = blockIdx.x;
    long base = (long)row * HID;
    for (int i = threadIdx.x; i < HID; i += 128) sh[i] = t[base + i];
    __syncthreads();
    float p[NCL];
    #pragma unroll
    for (int c = 0; c < NCL; c++) p[c] = 0.f;
    for (int i = threadIdx.x; i < HID; i += 128) {
        float tv = sh[i];
        const float* w = Wd + (long)i * NCL;
        #pragma unroll
        for (int c = 0; c < NCL; c++) p[c] = fmaf(tv, w[c], p[c]);
    }
    #pragma unroll
    for (int c = 0; c < NCL; c++)
        #pragma unroll
        for (int o = 16; o; o >>= 1) p[c] += __shfl_down_sync(0xffffffffu, p[c], o);
    if ((threadIdx.x & 31) == 0) {
        int w = threadIdx.x >> 5;
        #pragma unroll
        for (int c = 0; c < NCL; c++) wred[w][c] = p[c];
    }
    __syncthreads();
    if (threadIdx.x < NCL) {
        float v = wred[0][threadIdx.x] + wred[1][threadIdx.x]
                + wred[2][threadIdx.x] + wred[3][threadIdx.x] + bd[threadIdx.x];
        lg[threadIdx.x] = v;
        int oi = row * NCL + threadIdx.x;
        if (oi < logit_limit) out[oi] = v;
    }
    __syncthreads();
    if (threadIdx.x == 0) {
        float m = lg[0];
        #pragma unroll
        for (int c = 1; c < NCL; c++) m = fmaxf(m, lg[c]);
        float ssum = 0.f;
        #pragma unroll
        for (int c = 0; c < NCL; c++) ssum += expf(lg[c] - m);
        float lse = m + logf(ssum);
        float nl = lse - lg[labels[row]];
        nll[row] = nl * (float)am[row];
    }
}

__global__ void finalize_k(const float* __restrict__ nll, const int* __restrict__ am,
                           float* __restrict__ out, int loss_idx)
{
    __shared__ float red[8];
    float a = 0.f, bm = 0.f;
    for (int i = threadIdx.x; i < TOK; i += 256) { a += nll[i]; bm += (float)am[i]; }
    float sa = blk_sum(a, red);
    float sb = blk_sum(bm, red);
    if (threadIdx.x == 0 && loss_idx >= 0) out[loss_idx] = sa / fmaxf(sb, 1.0f);
}

// ------------------------------- host driver ----------------------------------
static inline JobDesc mkjob(const float* A, const float* B, float* C,
                            const float* bias, int M)
{
    JobDesc d; d.A = A; d.B = B; d.C = C; d.bias = bias; d.M = M; d.pad = 0;
    return d;
}

extern "C" void kernel_launch(void* const* d_in, const int* in_sizes, int n_in,
                              void* d_out, int out_size)
{
    (void)in_sizes; (void)n_in;
    const float* word_emb = (const float*)d_in[0];
    const float* emb_ln_s = (const float*)d_in[1];
    const float* emb_ln_b = (const float*)d_in[2];
    const float* rel_emb  = (const float*)d_in[3];
    const float* rel_ln_s = (const float*)d_in[4];
    const float* rel_ln_b = (const float*)d_in[5];
    const float* Wq = (const float*)d_in[6];
    const float* bq = (const float*)d_in[7];
    const float* Wk = (const float*)d_in[8];
    const float* bk = (const float*)d_in[9];
    const float* Wv = (const float*)d_in[10];
    const float* bv = (const float*)d_in[11];
    const float* Wo = (const float*)d_in[12];
    const float* bo = (const float*)d_in[13];
    const float* ln1_s = (const float*)d_in[14];
    const float* ln1_b = (const float*)d_in[15];
    const float* W1 = (const float*)d_in[16];
    const float* b1 = (const float*)d_in[17];
    const float* W2 = (const float*)d_in[18];
    const float* b2 = (const float*)d_in[19];
    const float* ln2_s = (const float*)d_in[20];
    const float* ln2_b = (const float*)d_in[21];
    const float* Wt = (const float*)d_in[22];
    const float* bt = (const float*)d_in[23];
    const float* tln_s = (const float*)d_in[24];
    const float* tln_b = (const float*)d_in[25];
    const float* Wd = (const float*)d_in[26];
    const float* bd = (const float*)d_in[27];
    const int* ids    = (const int*)d_in[28];
    const int* am     = (const int*)d_in[29];
    const int* labels = (const int*)d_in[30];
    float* out = (float*)d_out;

    float *x, *q, *k, *v, *rel, *pk, *pq, *sc, *c2p, *p2c, *ctx, *ff, *nll;
    int* idxm;
    cudaGetSymbolAddress((void**)&x,   g_x);
    cudaGetSymbolAddress((void**)&q,   g_q);
    cudaGetSymbolAddress((void**)&k,   g_k);
    cudaGetSymbolAddress((void**)&v,   g_v);
    cudaGetSymbolAddress((void**)&rel, g_rel);
    cudaGetSymbolAddress((void**)&pk,  g_pk);
    cudaGetSymbolAddress((void**)&pq,  g_pq);
    cudaGetSymbolAddress((void**)&sc,  g_sc);
    cudaGetSymbolAddress((void**)&c2p, g_c2p);
    cudaGetSymbolAddress((void**)&p2c, g_p2c);
    cudaGetSymbolAddress((void**)&ctx, g_ctx);
    cudaGetSymbolAddress((void**)&ff,  g_ff);
    cudaGetSymbolAddress((void**)&nll, g_nll);
    cudaGetSymbolAddress((void**)&idxm, g_idxm);

    cudaFuncSetAttribute(tgemm512_k<0,false,8>,  cudaFuncAttributeMaxDynamicSharedMemorySize, SMEM_BYTES2);
    cudaFuncSetAttribute(tgemm512_k<1,false,8>,  cudaFuncAttributeMaxDynamicSharedMemorySize, SMEM_BYTES2);
    cudaFuncSetAttribute(tgemm512_k<0,true,96>,  cudaFuncAttributeMaxDynamicSharedMemorySize, SMEM_BYTES2);
    cudaFuncSetAttribute(tgemm_k<0,false,32>,    cudaFuncAttributeMaxDynamicSharedMemorySize, SMEM_BYTES);

    build_idx_k<<<SEQ, 128>>>(idxm);
    embed_ln_k<<<TOK, 256>>>(word_emb, emb_ln_s, emb_ln_b, ids, am, x);
    add_ln_k<<<SEQ, 256>>>(nullptr, rel_emb, rel_ln_s, rel_ln_b, rel);

    // -- fixed job tables (same scratch addresses every layer) --
    JobsP<96> scJobs;
    for (int job = 0; job < 3; job++)
        for (int head = 0; head < 32; head++) {
            int b = head >> 4, h = head & 15;
            const float* Aj = (job < 2 ? q : k) + (long)b * SHs + h * HDD;
            const float* Bj;
            if (job == 0)      Bj = k  + (long)b * SHs + h * HDD;
            else if (job == 1) Bj = pk + h * HDD;
            else               Bj = pq + h * HDD;
            float* Cj = (job == 0 ? sc : job == 1 ? c2p : p2c) + (long)head * HSC;
            scJobs.j[job * 32 + head] = mkjob(Aj, Bj, Cj, nullptr, 512);
        }
    JobsP<32> ctxJobs;
    for (int head = 0; head < 32; head++) {
        int b = head >> 4, h = head & 15;
        ctxJobs.j[head] = mkjob(sc + (long)head * HSC,
                                v + (long)b * SHs + h * HDD,
                                ctx + (long)b * SHs + h * HDD, nullptr, 512);
    }

    for (int l = 0; l < NL; l++) {
        const float* Wq_l = Wq + (long)l * HID * HID;
        const float* Wk_l = Wk + (long)l * HID * HID;
        const float* Wv_l = Wv + (long)l * HID * HID;
        const float* Wo_l = Wo + (long)l * HID * HID;
        const float* bq_l = bq + l * HID;
        const float* bk_l = bk + l * HID;
        const float* bv_l = bv + l * HID;
        const float* bo_l = bo + l * HID;
        const float* W1_l = W1 + (long)l * HID * FFD;
        const float* b1_l = b1 + l * FFD;
        const float* W2_l = W2 + (long)l * FFD * HID;
        const float* b2_l = b2 + l * HID;

        // fused Q/K/V projections + positional K/Q (share_att_key)
        JobsP<8> pj;
        pj.j[0] = mkjob(x,   Wq_l, q,  bq_l, 1024);
        pj.j[1] = mkjob(x,   Wk_l, k,  bk_l, 1024);
        pj.j[2] = mkjob(x,   Wv_l, v,  bv_l, 1024);
        pj.j[3] = mkjob(rel, Wk_l, pk, bk_l, 512);
        pj.j[4] = mkjob(rel, Wq_l, pq, bq_l, 512);
        tgemm512_k<0,false,8><<<dim3(8,8,5), 512, SMEM_BYTES2>>>(pj, HID, HID, HID, HID);

        // fused attention GEMMs: qk, c2p, p2c  (A @ B^T per (b,h))
        tgemm512_k<0,true,96><<<dim3(4,4,96), 512, SMEM_BYTES2>>>(scJobs, HDD, HID, HID, 512);

        // combine disentangled biases + mask + softmax (in-place -> probs)
        attn_softmax_k<<<dim3(SEQ, BSZ * NHD), 128>>>(sc, c2p, p2c, idxm, am);

        // ctx = probs @ V (per head, N=64)
        tgemm_k<0,false,32><<<dim3(1,4,32), 256, SMEM_BYTES>>>(ctxJobs, SEQ, 512, HID, HID);

        // output proj + residual LN
        JobsP<8> oj; oj.j[0] = mkjob(ctx, Wo_l, ff, bo_l, 1024);
        tgemm512_k<0,false,8><<<dim3(8,8,1), 512, SMEM_BYTES2>>>(oj, HID, HID, HID, HID);
        add_ln_k<<<TOK, 256>>>(x, ff, ln1_s + l * HID, ln1_b + l * HID, x);

        // FFN
        JobsP<8> f1; f1.j[0] = mkjob(x, W1_l, ff, b1_l, 1024);
        tgemm512_k<1,false,8><<<dim3(32,8,1), 512, SMEM_BYTES2>>>(f1, HID, HID, FFD, FFD);
        JobsP<8> f2; f2.j[0] = mkjob(ff, W2_l, ctx, b2_l, 1024);
        tgemm512_k<0,false,8><<<dim3(8,8,1), 512, SMEM_BYTES2>>>(f2, FFD, FFD, HID, HID);
        add_ln_k<<<TOK, 256>>>(x, ctx, ln2_s + l * HID, ln2_b + l * HID, x);
    }

    // transform head: LN(gelu(x @ Wt + bt))
    JobsP<8> tj; tj.j[0] = mkjob(x, Wt, ff, bt, 1024);
    tgemm512_k<1,false,8><<<dim3(8,8,1), 512, SMEM_BYTES2>>>(tj, HID, HID, HID, HID);
    add_ln_k<<<TOK, 256>>>(nullptr, ff, tln_s, tln_b, q);   // reuse q buffer as t

    int logits_n = TOK * NCL;                               // 14336
    int logit_limit = (out_size > 1) ? (out_size < logits_n ? out_size : logits_n) : 0;
    int loss_idx = (out_size == 1) ? 0 : (out_size > logits_n ? logits_n : -1);
    decoder_k<<<TOK, 128>>>(q, Wd, bd, labels, am, out, logit_limit, nll);
    finalize_k<<<1, 256>>>(nll, am, out, loss_idx);
}

// round 11
// speedup vs baseline: 1.8470x; 1.8470x over previous
#include <cuda_runtime.h>
#include <cuda_bf16.h>
#include <math.h>
#include <stdint.h>

// Problem dims
#define BSZ 2
#define SEQ 512
#define HID 1024
#define NHD 16
#define HDD 64
#define NL  4
#define FFD 4096
#define NCL 14
#define TOK (BSZ*SEQ)          // 1024
#define SHs (SEQ*HID)          // 524288
#define HSC (SEQ*SEQ)          // 262144

// ---------------- scratch (device globals: no cudaMalloc allowed) -------------
__device__ float g_x[TOK*HID];
__device__ float g_q[TOK*HID];
__device__ float g_k[TOK*HID];
__device__ float g_v[TOK*HID];
__device__ float g_rel[SEQ*HID];
__device__ float g_pk[SEQ*HID];
__device__ float g_pq[SEQ*HID];
__device__ float g_sc[BSZ*NHD*SEQ*SEQ];
__device__ float g_c2p[BSZ*NHD*SEQ*SEQ];
__device__ float g_p2c[BSZ*NHD*SEQ*SEQ];
__device__ float g_ctx[TOK*HID];
__device__ float g_ff[TOK*FFD];
__device__ int   g_idxm[SEQ*SEQ];
__device__ float g_nll[TOK];

// ---------------- job descriptors (passed in kernel params) -------------------
struct JobDesc { const float* A; const float* B; float* C; const float* bias; int M; int pad; };
template<int NJ> struct JobsP { JobDesc j[NJ]; };

// ---------------- block reduction helper --------------------------------------
__device__ __forceinline__ float blk_sum(float v, float* red) {
    #pragma unroll
    for (int o = 16; o; o >>= 1) v += __shfl_down_sync(0xffffffffu, v, o);
    int w = threadIdx.x >> 5, lane = threadIdx.x & 31;
    int nw = blockDim.x >> 5;
    __syncthreads();
    if (lane == 0) red[w] = v;
    __syncthreads();
    if (threadIdx.x == 0) { float s = 0.f; for (int i = 0; i < nw; i++) s += red[i]; red[0] = s; }
    __syncthreads();
    return red[0];
}

// ---------------- bf16 split helpers ------------------------------------------
__device__ __forceinline__ void split2(float x0, float x1, uint32_t& h, uint32_t& l) {
    __nv_bfloat16 h0 = __float2bfloat16_rn(x0);
    __nv_bfloat16 h1 = __float2bfloat16_rn(x1);
    float r0 = x0 - __bfloat162float(h0);
    float r1 = x1 - __bfloat162float(h1);
    __nv_bfloat162 hp; hp.x = h0; hp.y = h1;
    __nv_bfloat162 lp; lp.x = __float2bfloat16_rn(r0); lp.y = __float2bfloat16_rn(r1);
    h = *(uint32_t*)&hp;
    l = *(uint32_t*)&lp;
}
__device__ __forceinline__ uint32_t pack_hi2(float x0, float x1) {
    __nv_bfloat162 hp; hp.x = __float2bfloat16_rn(x0); hp.y = __float2bfloat16_rn(x1);
    return *(uint32_t*)&hp;
}
__device__ __forceinline__ uint32_t pack_lo2(float x0, float x1) {
    __nv_bfloat16 h0 = __float2bfloat16_rn(x0);
    __nv_bfloat16 h1 = __float2bfloat16_rn(x1);
    __nv_bfloat162 lp;
    lp.x = __float2bfloat16_rn(x0 - __bfloat162float(h0));
    lp.y = __float2bfloat16_rn(x1 - __bfloat162float(h1));
    return *(uint32_t*)&lp;
}

__device__ __forceinline__ void mma_bf16(float* d, const uint32_t* a, const uint32_t* b) {
    asm volatile(
        "mma.sync.aligned.m16n8k16.row.col.f32.bf16.bf16.f32 "
        "{%0,%1,%2,%3}, {%4,%5,%6,%7}, {%8,%9}, {%0,%1,%2,%3};\n"
        : "+f"(d[0]), "+f"(d[1]), "+f"(d[2]), "+f"(d[3])
        : "r"(a[0]), "r"(a[1]), "r"(a[2]), "r"(a[3]), "r"(b[0]), "r"(b[1]));
}

// ======== 128x64 bf16 tensor-core GEMM (3xBF16 compensated, 256 threads) ======
// Block tile 128(M) x 64(N), BK=16, 8 warps (4x2), warp tile 32x32.
// One m16n8k16 MMA consumes a full 16-float k-tile per (mt,nt) fragment pair.
// TB=true -> B given as [N,K] row-major (computes A @ B^T).
// Smem: packed bf16x2 along k, row stride 12 u32 (conflict-free fragment LDS).
template<int ACT, bool TB, int NJ>
__global__ __launch_bounds__(256)
void bgemm_k(JobsP<NJ> P, int K, int lda, int ldb, int ldc)
{
    const JobDesc jd = P.j[blockIdx.z];
    const int m0 = blockIdx.y << 7;
    if (m0 >= jd.M) return;
    const float* __restrict__ A  = jd.A;
    const float* __restrict__ Bm = jd.B;
    float* __restrict__ C = jd.C;
    const float* bias = jd.bias;
    const int n0 = blockIdx.x << 6;

    __shared__ uint32_t AhS[2][128][12];
    __shared__ uint32_t AlS[2][128][12];
    __shared__ uint32_t BhS[2][64][12];
    __shared__ uint32_t BlS[2][64][12];

    const int tid  = threadIdx.x;
    const int warp = tid >> 5, lane = tid & 31;
    const int wm = warp >> 1;          // 0..3
    const int wn = warp & 1;           // 0..1
    const int g  = lane >> 2;          // 0..7
    const int t  = lane & 3;           // 0..3

    // A staging: thread covers row ar, floats acf..acf+7 (-> 4 packed u32)
    const int ar  = tid >> 1;                // 0..127
    const int acf = (tid & 1) << 3;          // 0 or 8
    // B staging (TB): row brn, floats bckf..+3 (-> 2 packed u32)
    const int brn  = tid >> 2;               // 0..63
    const int bckf = (tid & 3) << 2;         // 0,4,8,12
    // B staging (!TB): warp = k-pair index, lane&15 = n-group, lane>>4 = lo-half
    const int w8   = warp;                   // 0..7 -> k pair
    const int ng   = lane & 15;              // n group (4 floats)
    const int isLo = lane >> 4;

    float acc[2][4][4] = {};
    float4 ra0, ra1, rb0, rb1;

    // ---- prologue: k-tile 0 -> regs ----
    {
        const float* Ap = A + (long)(m0 + ar) * lda + acf;
        ra0 = *(const float4*)Ap; ra1 = *(const float4*)(Ap + 4);
        if (TB) {
            rb0 = *(const float4*)(Bm + (long)(n0 + brn) * ldb + bckf);
        } else {
            const float* Bp = Bm + (long)(2 * w8) * ldb + n0 + (ng << 2);
            rb0 = *(const float4*)Bp;
            rb1 = *(const float4*)(Bp + ldb);
        }
    }
    // ---- split + store stage 0 ----
    {
        uint4 h4, l4;
        split2(ra0.x, ra0.y, h4.x, l4.x); split2(ra0.z, ra0.w, h4.y, l4.y);
        split2(ra1.x, ra1.y, h4.z, l4.z); split2(ra1.z, ra1.w, h4.w, l4.w);
        *(uint4*)&AhS[0][ar][acf >> 1] = h4;
        *(uint4*)&AlS[0][ar][acf >> 1] = l4;
        if (TB) {
            uint32_t h0, l0, h1, l1;
            split2(rb0.x, rb0.y, h0, l0); split2(rb0.z, rb0.w, h1, l1);
            *(uint2*)&BhS[0][brn][bckf >> 1] = make_uint2(h0, h1);
            *(uint2*)&BlS[0][brn][bckf >> 1] = make_uint2(l0, l1);
        } else {
            float v0[4] = {rb0.x, rb0.y, rb0.z, rb0.w};
            float v1[4] = {rb1.x, rb1.y, rb1.z, rb1.w};
            int sw = w8 ^ ((ng & 3) << 1);
            #pragma unroll
            for (int j = 0; j < 4; j++) {
                int n = (ng << 2) + j;
                if (isLo) BlS[0][n][sw] = pack_lo2(v0[j], v1[j]);
                else      BhS[0][n][sw] = pack_hi2(v0[j], v1[j]);
            }
        }
    }
    __syncthreads();

    const int KT = K >> 4;
    for (int kt = 0; kt < KT; kt++) {
        const int s = kt & 1;
        const bool more = (kt + 1 < KT);
        if (more) {
            int k0 = (kt + 1) << 4;
            const float* Ap = A + (long)(m0 + ar) * lda + k0 + acf;
            ra0 = *(const float4*)Ap; ra1 = *(const float4*)(Ap + 4);
            if (TB) {
                rb0 = *(const float4*)(Bm + (long)(n0 + brn) * ldb + k0 + bckf);
            } else {
                const float* Bp = Bm + (long)(k0 + 2 * w8) * ldb + n0 + (ng << 2);
                rb0 = *(const float4*)Bp;
                rb1 = *(const float4*)(Bp + ldb);
            }
        }
        // ---- fragments + 24 MMAs on stage s (one k16 step) ----
        {
            uint32_t ah[2][4], al[2][4], bh[4][2], bl[4][2];
            #pragma unroll
            for (int mt = 0; mt < 2; mt++) {
                int mr = (wm << 5) + (mt << 4);
                ah[mt][0] = AhS[s][mr + g][t];
                ah[mt][1] = AhS[s][mr + g + 8][t];
                ah[mt][2] = AhS[s][mr + g][t + 4];
                ah[mt][3] = AhS[s][mr + g + 8][t + 4];
                al[mt][0] = AlS[s][mr + g][t];
                al[mt][1] = AlS[s][mr + g + 8][t];
                al[mt][2] = AlS[s][mr + g][t + 4];
                al[mt][3] = AlS[s][mr + g + 8][t + 4];
            }
            #pragma unroll
            for (int nt = 0; nt < 4; nt++) {
                int nc = (wn << 5) + (nt << 3) + g;
                int idx0 = TB ? t : (t ^ (((nc >> 2) & 3) << 1));
                bh[nt][0] = BhS[s][nc][idx0];
                bh[nt][1] = BhS[s][nc][idx0 ^ 4];
                bl[nt][0] = BlS[s][nc][idx0];
                bl[nt][1] = BlS[s][nc][idx0 ^ 4];
            }
            #pragma unroll
            for (int mt = 0; mt < 2; mt++)
                #pragma unroll
                for (int nt = 0; nt < 4; nt++) mma_bf16(acc[mt][nt], ah[mt], bh[nt]);
            #pragma unroll
            for (int mt = 0; mt < 2; mt++)
                #pragma unroll
                for (int nt = 0; nt < 4; nt++) mma_bf16(acc[mt][nt], ah[mt], bl[nt]);
            #pragma unroll
            for (int mt = 0; mt < 2; mt++)
                #pragma unroll
                for (int nt = 0; nt < 4; nt++) mma_bf16(acc[mt][nt], al[mt], bh[nt]);
        }
        if (more) {
            const int s2 = (kt + 1) & 1;
            uint4 h4, l4;
            split2(ra0.x, ra0.y, h4.x, l4.x); split2(ra0.z, ra0.w, h4.y, l4.y);
            split2(ra1.x, ra1.y, h4.z, l4.z); split2(ra1.z, ra1.w, h4.w, l4.w);
            *(uint4*)&AhS[s2][ar][acf >> 1] = h4;
            *(uint4*)&AlS[s2][ar][acf >> 1] = l4;
            if (TB) {
                uint32_t h0, l0, h1, l1;
                split2(rb0.x, rb0.y, h0, l0); split2(rb0.z, rb0.w, h1, l1);
                *(uint2*)&BhS[s2][brn][bckf >> 1] = make_uint2(h0, h1);
                *(uint2*)&BlS[s2][brn][bckf >> 1] = make_uint2(l0, l1);
            } else {
                float v0[4] = {rb0.x, rb0.y, rb0.z, rb0.w};
                float v1[4] = {rb1.x, rb1.y, rb1.z, rb1.w};
                int sw = w8 ^ ((ng & 3) << 1);
                #pragma unroll
                for (int j = 0; j < 4; j++) {
                    int n = (ng << 2) + j;
                    if (isLo) BlS[s2][n][sw] = pack_lo2(v0[j], v1[j]);
                    else      BhS[s2][n][sw] = pack_hi2(v0[j], v1[j]);
                }
            }
        }
        __syncthreads();
    }

    // epilogue (C fragment layout identical to m16n8k8 path)
    #pragma unroll
    for (int mt = 0; mt < 2; mt++) {
        #pragma unroll
        for (int nt = 0; nt < 4; nt++) {
            int col = n0 + (wn << 5) + (nt << 3) + (t << 1);
            float b0 = bias ? bias[col]     : 0.f;
            float b1 = bias ? bias[col + 1] : 0.f;
            #pragma unroll
            for (int half = 0; half < 2; half++) {
                int row = m0 + (wm << 5) + (mt << 4) + g + (half << 3);
                float v0 = acc[mt][nt][half * 2 + 0] + b0;
                float v1 = acc[mt][nt][half * 2 + 1] + b1;
                if (ACT == 1) {
                    v0 = 0.5f * v0 * (1.0f + erff(v0 * 0.70710678118654752f));
                    v1 = 0.5f * v1 * (1.0f + erff(v1 * 0.70710678118654752f));
                }
                *(float2*)(C + (long)row * ldc + col) = make_float2(v0, v1);
            }
        }
    }
}

// ---------------- embedding: x = LN(word_emb[id]) * maskf ---------------------
__global__ void embed_ln_k(const float* __restrict__ emb,
                           const float* __restrict__ s, const float* __restrict__ b,
                           const int* __restrict__ ids, const int* __restrict__ am,
                           float* __restrict__ out)
{
    __shared__ float sh[HID];
    __shared__ float red[8];
    int tok = blockIdx.x;
    long ebase = (long)ids[tok] * HID;
    float m = (float)am[tok];
    float ls = 0.f;
    for (int i = threadIdx.x; i < HID; i += blockDim.x) { float v = emb[ebase + i]; sh[i] = v; ls += v; }
    __syncthreads();
    float mu = blk_sum(ls, red) * (1.0f / HID);
    float lv = 0.f;
    for (int i = threadIdx.x; i < HID; i += blockDim.x) { float d = sh[i] - mu; lv += d * d; }
    float var = blk_sum(lv, red) * (1.0f / HID);
    float r = rsqrtf(var + 1e-7f);
    long obase = (long)tok * HID;
    for (int i = threadIdx.x; i < HID; i += blockDim.x)
        out[obase + i] = ((sh[i] - mu) * r * s[i] + b[i]) * m;
}

// ---------------- residual + LN: out = LN((res?) + t) -------------------------
__global__ void add_ln_k(const float* res, const float* __restrict__ t,
                         const float* __restrict__ s, const float* __restrict__ b,
                         float* out)
{
    __shared__ float sh[HID];
    __shared__ float red[8];
    long base = (long)blockIdx.x * HID;
    float ls = 0.f;
    for (int i = threadIdx.x; i < HID; i += blockDim.x) {
        float v = t[base + i];
        if (res) v += res[base + i];
        sh[i] = v; ls += v;
    }
    __syncthreads();
    float mu = blk_sum(ls, red) * (1.0f / HID);
    float lv = 0.f;
    for (int i = threadIdx.x; i < HID; i += blockDim.x) { float d = sh[i] - mu; lv += d * d; }
    float var = blk_sum(lv, red) * (1.0f / HID);
    float r = rsqrtf(var + 1e-7f);
    for (int i = threadIdx.x; i < HID; i += blockDim.x)
        out[base + i] = (sh[i] - mu) * r * s[i] + b[i];
}

// ---------------- DeBERTa log-bucket relative index ---------------------------
__global__ void build_idx_k(int* __restrict__ idxm)
{
    int q = blockIdx.x;
    const int mid = 128;
    for (int k = threadIdx.x; k < SEQ; k += blockDim.x) {
        int rel = q - k;
        int a = (rel < mid && rel > -mid) ? (mid - 1) : (rel < 0 ? -rel : rel);
        int bucket;
        if (a <= mid) bucket = rel;
        else {
            float lp = ceilf(logf((float)a / (float)mid) / logf(511.0f / (float)mid) * (float)(mid - 1))
                       + (float)mid;
            float sgn = (rel > 0) ? 1.f : ((rel < 0) ? -1.f : 0.f);
            bucket = (int)(lp * sgn);
        }
        int J = bucket + 256;
        J = J < 0 ? 0 : (J > 511 ? 511 : J);
        idxm[q * SEQ + k] = J;
    }
}

// ------- combine + mask + softmax:  probs = softmax((qk + c2p[J] + p2c[J])/scale)
__global__ void attn_softmax_k(float* __restrict__ sc, const float* __restrict__ c2p,
                               const float* __restrict__ p2c, const int* __restrict__ idxm,
                               const int* __restrict__ am)
{
    __shared__ float red[4];
    int q = blockIdx.x, z = blockIdx.y;
    int b = z >> 4;
    long ro = ((long)z * SEQ + q) * (long)SEQ;
    float* row = sc + ro;
    const float* cr = c2p + ro;
    const float* pb = p2c + (long)z * SEQ * 512;
    int mq = am[b * SEQ + q];
    const float scale = sqrtf(3.0f * (float)HDD);
    float vals[4]; int msk[4];
    float mx = -3.402823466e38f;
    #pragma unroll
    for (int t = 0; t < 4; t++) {
        int k = threadIdx.x + t * 128;
        int J = idxm[q * SEQ + k];
        float v = (row[k] + cr[J] + pb[(long)k * 512 + J]) / scale;
        int mk = mq & am[b * SEQ + k];
        vals[t] = v; msk[t] = mk;
        if (mk) mx = fmaxf(mx, v);
    }
    #pragma unroll
    for (int o = 16; o; o >>= 1) mx = fmaxf(mx, __shfl_down_sync(0xffffffffu, mx, o));
    if ((threadIdx.x & 31) == 0) red[threadIdx.x >> 5] = mx;
    __syncthreads();
    mx = fmaxf(fmaxf(red[0], red[1]), fmaxf(red[2], red[3]));
    float ls = 0.f;
    #pragma unroll
    for (int t = 0; t < 4; t++) {
        float e = msk[t] ? expf(vals[t] - mx) : 0.f;
        vals[t] = e; ls += e;
    }
    __syncthreads();
    #pragma unroll
    for (int o = 16; o; o >>= 1) ls += __shfl_down_sync(0xffffffffu, ls, o);
    if ((threadIdx.x & 31) == 0) red[threadIdx.x >> 5] = ls;
    __syncthreads();
    float sum = red[0] + red[1] + red[2] + red[3];
    float inv = sum > 0.f ? 1.0f / sum : 0.f;
    #pragma unroll
    for (int t = 0; t < 4; t++) row[threadIdx.x + t * 128] = vals[t] * inv;
}

// ---------------- decoder (N=14) + per-row masked NLL -------------------------
__global__ void decoder_k(const float* __restrict__ t, const float* __restrict__ Wd,
                          const float* __restrict__ bd, const int* __restrict__ labels,
                          const int* __restrict__ am, float* __restrict__ out,
                          int logit_limit, float* __restrict__ nll)
{
    __shared__ float sh[HID];
    __shared__ float wred[4][NCL];
    __shared__ float lg[NCL];
    int row = blockIdx.x;
    long base = (long)row * HID;
    for (int i = threadIdx.x; i < HID; i += 128) sh[i] = t[base + i];
    __syncthreads();
    float p[NCL];
    #pragma unroll
    for (int c = 0; c < NCL; c++) p[c] = 0.f;
    for (int i = threadIdx.x; i < HID; i += 128) {
        float tv = sh[i];
        const float* w = Wd + (long)i * NCL;
        #pragma unroll
        for (int c = 0; c < NCL; c++) p[c] = fmaf(tv, w[c], p[c]);
    }
    #pragma unroll
    for (int c = 0; c < NCL; c++)
        #pragma unroll
        for (int o = 16; o; o >>= 1) p[c] += __shfl_down_sync(0xffffffffu, p[c], o);
    if ((threadIdx.x & 31) == 0) {
        int w = threadIdx.x >> 5;
        #pragma unroll
        for (int c = 0; c < NCL; c++) wred[w][c] = p[c];
    }
    __syncthreads();
    if (threadIdx.x < NCL) {
        float v = wred[0][threadIdx.x] + wred[1][threadIdx.x]
                + wred[2][threadIdx.x] + wred[3][threadIdx.x] + bd[threadIdx.x];
        lg[threadIdx.x] = v;
        int oi = row * NCL + threadIdx.x;
        if (oi < logit_limit) out[oi] = v;
    }
    __syncthreads();
    if (threadIdx.x == 0) {
        float m = lg[0];
        #pragma unroll
        for (int c = 1; c < NCL; c++) m = fmaxf(m, lg[c]);
        float ssum = 0.f;
        #pragma unroll
        for (int c = 0; c < NCL; c++) ssum += expf(lg[c] - m);
        float lse = m + logf(ssum);
        float nl = lse - lg[labels[row]];
        nll[row] = nl * (float)am[row];
    }
}

__global__ void finalize_k(const float* __restrict__ nll, const int* __restrict__ am,
                           float* __restrict__ out, int loss_idx)
{
    __shared__ float red[8];
    float a = 0.f, bm = 0.f;
    for (int i = threadIdx.x; i < TOK; i += 256) { a += nll[i]; bm += (float)am[i]; }
    float sa = blk_sum(a, red);
    float sb = blk_sum(bm, red);
    if (threadIdx.x == 0 && loss_idx >= 0) out[loss_idx] = sa / fmaxf(sb, 1.0f);
}

// ------------------------------- host driver ----------------------------------
static inline JobDesc mkjob(const float* A, const float* B, float* C,
                            const float* bias, int M)
{
    JobDesc d; d.A = A; d.B = B; d.C = C; d.bias = bias; d.M = M; d.pad = 0;
    return d;
}

extern "C" void kernel_launch(void* const* d_in, const int* in_sizes, int n_in,
                              void* d_out, int out_size)
{
    (void)in_sizes; (void)n_in;
    const float* word_emb = (const float*)d_in[0];
    const float* emb_ln_s = (const float*)d_in[1];
    const float* emb_ln_b = (const float*)d_in[2];
    const float* rel_emb  = (const float*)d_in[3];
    const float* rel_ln_s = (const float*)d_in[4];
    const float* rel_ln_b = (const float*)d_in[5];
    const float* Wq = (const float*)d_in[6];
    const float* bq = (const float*)d_in[7];
    const float* Wk = (const float*)d_in[8];
    const float* bk = (const float*)d_in[9];
    const float* Wv = (const float*)d_in[10];
    const float* bv = (const float*)d_in[11];
    const float* Wo = (const float*)d_in[12];
    const float* bo = (const float*)d_in[13];
    const float* ln1_s = (const float*)d_in[14];
    const float* ln1_b = (const float*)d_in[15];
    const float* W1 = (const float*)d_in[16];
    const float* b1 = (const float*)d_in[17];
    const float* W2 = (const float*)d_in[18];
    const float* b2 = (const float*)d_in[19];
    const float* ln2_s = (const float*)d_in[20];
    const float* ln2_b = (const float*)d_in[21];
    const float* Wt = (const float*)d_in[22];
    const float* bt = (const float*)d_in[23];
    const float* tln_s = (const float*)d_in[24];
    const float* tln_b = (const float*)d_in[25];
    const float* Wd = (const float*)d_in[26];
    const float* bd = (const float*)d_in[27];
    const int* ids    = (const int*)d_in[28];
    const int* am     = (const int*)d_in[29];
    const int* labels = (const int*)d_in[30];
    float* out = (float*)d_out;

    float *x, *q, *k, *v, *rel, *pk, *pq, *sc, *c2p, *p2c, *ctx, *ff, *nll;
    int* idxm;
    cudaGetSymbolAddress((void**)&x,   g_x);
    cudaGetSymbolAddress((void**)&q,   g_q);
    cudaGetSymbolAddress((void**)&k,   g_k);
    cudaGetSymbolAddress((void**)&v,   g_v);
    cudaGetSymbolAddress((void**)&rel, g_rel);
    cudaGetSymbolAddress((void**)&pk,  g_pk);
    cudaGetSymbolAddress((void**)&pq,  g_pq);
    cudaGetSymbolAddress((void**)&sc,  g_sc);
    cudaGetSymbolAddress((void**)&c2p, g_c2p);
    cudaGetSymbolAddress((void**)&p2c, g_p2c);
    cudaGetSymbolAddress((void**)&ctx, g_ctx);
    cudaGetSymbolAddress((void**)&ff,  g_ff);
    cudaGetSymbolAddress((void**)&nll, g_nll);
    cudaGetSymbolAddress((void**)&idxm, g_idxm);

    build_idx_k<<<SEQ, 128>>>(idxm);
    embed_ln_k<<<TOK, 256>>>(word_emb, emb_ln_s, emb_ln_b, ids, am, x);
    add_ln_k<<<SEQ, 256>>>(nullptr, rel_emb, rel_ln_s, rel_ln_b, rel);

    // -- fixed job tables (same scratch addresses every layer) --
    JobsP<96> scJobs;
    for (int job = 0; job < 3; job++)
        for (int head = 0; head < 32; head++) {
            int b = head >> 4, h = head & 15;
            const float* Aj = (job < 2 ? q : k) + (long)b * SHs + h * HDD;
            const float* Bj;
            if (job == 0)      Bj = k  + (long)b * SHs + h * HDD;
            else if (job == 1) Bj = pk + h * HDD;
            else               Bj = pq + h * HDD;
            float* Cj = (job == 0 ? sc : job == 1 ? c2p : p2c) + (long)head * HSC;
            scJobs.j[job * 32 + head] = mkjob(Aj, Bj, Cj, nullptr, 512);
        }
    JobsP<32> ctxJobs;
    for (int head = 0; head < 32; head++) {
        int b = head >> 4, h = head & 15;
        ctxJobs.j[head] = mkjob(sc + (long)head * HSC,
                                v + (long)b * SHs + h * HDD,
                                ctx + (long)b * SHs + h * HDD, nullptr, 512);
    }

    for (int l = 0; l < NL; l++) {
        const float* Wq_l = Wq + (long)l * HID * HID;
        const float* Wk_l = Wk + (long)l * HID * HID;
        const float* Wv_l = Wv + (long)l * HID * HID;
        const float* Wo_l = Wo + (long)l * HID * HID;
        const float* bq_l = bq + l * HID;
        const float* bk_l = bk + l * HID;
        const float* bv_l = bv + l * HID;
        const float* bo_l = bo + l * HID;
        const float* W1_l = W1 + (long)l * HID * FFD;
        const float* b1_l = b1 + l * FFD;
        const float* W2_l = W2 + (long)l * FFD * HID;
        const float* b2_l = b2 + l * HID;

        // fused Q/K/V projections + positional K/Q (share_att_key)
        JobsP<8> pj;
        pj.j[0] = mkjob(x,   Wq_l, q,  bq_l, 1024);
        pj.j[1] = mkjob(x,   Wk_l, k,  bk_l, 1024);
        pj.j[2] = mkjob(x,   Wv_l, v,  bv_l, 1024);
        pj.j[3] = mkjob(rel, Wk_l, pk, bk_l, 512);
        pj.j[4] = mkjob(rel, Wq_l, pq, bq_l, 512);
        bgemm_k<0,false,8><<<dim3(16,8,5), 256>>>(pj, HID, HID, HID, HID);

        // fused attention GEMMs: qk, c2p, p2c  (A @ B^T per (b,h))
        bgemm_k<0,true,96><<<dim3(8,4,96), 256>>>(scJobs, HDD, HID, HID, 512);

        // combine disentangled biases + mask + softmax (in-place -> probs)
        attn_softmax_k<<<dim3(SEQ, BSZ * NHD), 128>>>(sc, c2p, p2c, idxm, am);

        // ctx = probs @ V (per head, N=64)
        bgemm_k<0,false,32><<<dim3(1,4,32), 256>>>(ctxJobs, SEQ, 512, HID, HID);

        // output proj + residual LN
        JobsP<8> oj; oj.j[0] = mkjob(ctx, Wo_l, ff, bo_l, 1024);
        bgemm_k<0,false,8><<<dim3(16,8,1), 256>>>(oj, HID, HID, HID, HID);
        add_ln_k<<<TOK, 256>>>(x, ff, ln1_s + l * HID, ln1_b + l * HID, x);

        // FFN
        JobsP<8> f1; f1.j[0] = mkjob(x, W1_l, ff, b1_l, 1024);
        bgemm_k<1,false,8><<<dim3(64,8,1), 256>>>(f1, HID, HID, FFD, FFD);
        JobsP<8> f2; f2.j[0] = mkjob(ff, W2_l, ctx, b2_l, 1024);
        bgemm_k<0,false,8><<<dim3(16,8,1), 256>>>(f2, FFD, FFD, HID, HID);
        add_ln_k<<<TOK, 256>>>(x, ctx, ln2_s + l * HID, ln2_b + l * HID, x);
    }

    // transform head: LN(gelu(x @ Wt + bt))
    JobsP<8> tj; tj.j[0] = mkjob(x, Wt, ff, bt, 1024);
    bgemm_k<1,false,8><<<dim3(16,8,1), 256>>>(tj, HID, HID, HID, HID);
    add_ln_k<<<TOK, 256>>>(nullptr, ff, tln_s, tln_b, q);   // reuse q buffer as t

    int logits_n = TOK * NCL;                               // 14336
    int logit_limit = (out_size > 1) ? (out_size < logits_n ? out_size : logits_n) : 0;
    int loss_idx = (out_size == 1) ? 0 : (out_size > logits_n ? logits_n : -1);
    decoder_k<<<TOK, 128>>>(q, Wd, bd, labels, am, out, logit_limit, nll);
    finalize_k<<<1, 256>>>(nll, am, out, loss_idx);
}